// round 15
// baseline (speedup 1.0000x reference)
#include <cuda_runtime.h>
#include <cstdint>

// RiemannSolver R14: TILE=512 (2 cells/thread, 2 MMA subtiles/warp).
// Both gather chains issue up-front (ILP on the ~1200cyc bucket->cell chain),
// weight-copy overlaps the index-load latency, CTA count halves.
// Proven R13 m16n8k8 MMA + split-N + MUFU tanh epilogue unchanged.

typedef unsigned long long u64;

#define NC 1048576
#define GAMMA_F 1.6666666666666667f
#define TILE 512
#define KDIM 24
#define SA_STRIDE 28      // floats/row: conflict-free STS.128 + A-frag LDS
#define SB_STRIDE 72      // floats/row: 72%32==8 -> conflict-free B-frag LDS

__device__ int g_cnt[4];
__device__ int g_done;
__device__ int g_bucket[3 * NC];
__device__ float g_pB[3][KDIM * SB_STRIDE];
__device__ float g_pW2[3][256];
__device__ float g_pB2[3][4];

__device__ __forceinline__ uint32_t f2tf32(float x) {
    uint32_t r;
    asm("cvt.rna.tf32.f32 %0, %1;" : "=r"(r) : "f"(x));
    return r;
}

// m16n8k8 tf32: A: a0=(g,tig) a1=(g+8,tig) a2=(g,tig+4) a3=(g+8,tig+4)
//               B: b0=(tig,g) b1=(tig+4,g)
//               D: d0=(g,2tig) d1=(g,2tig+1) d2=(g+8,2tig) d3=(g+8,2tig+1)
__device__ __forceinline__ void mma_tf32_k8(float* d, uint32_t a0, uint32_t a1,
                                            uint32_t a2, uint32_t a3,
                                            uint32_t b0, uint32_t b1) {
    asm volatile(
        "mma.sync.aligned.m16n8k8.row.col.f32.tf32.tf32.f32 "
        "{%0,%1,%2,%3}, {%4,%5,%6,%7}, {%8,%9}, {%0,%1,%2,%3};"
        : "+f"(d[0]), "+f"(d[1]), "+f"(d[2]), "+f"(d[3])
        : "r"(a0), "r"(a1), "r"(a2), "r"(a3), "r"(b0), "r"(b1));
}

__device__ __forceinline__ float tanh_mufu(float x) {
    float r;
    asm("tanh.approx.f32 %0, %1;" : "=f"(r) : "f"(x));
    return r;
}

// ---------------------------------------------------------------------------
__global__ __launch_bounds__(256)
void k_classify(const float* __restrict__ P, const float* __restrict__ U,
                const float* __restrict__ F, const float* __restrict__ cmax,
                const float* __restrict__ cmin,
                const float* __restrict__ W1_0, const float* __restrict__ b1_0,
                const float* __restrict__ W2_0, const float* __restrict__ b2_0,
                const float* __restrict__ W1_1, const float* __restrict__ b1_1,
                const float* __restrict__ W2_1, const float* __restrict__ b2_1,
                const float* __restrict__ W1_2, const float* __restrict__ b1_2,
                const float* __restrict__ W2_2, const float* __restrict__ b2_2,
                float* __restrict__ out, int N) {
    __shared__ int shCnt[3];
    __shared__ int shBase[3];
    __shared__ int wBase[8][3];
    int tid = threadIdx.x;
    if (tid < 3) shCnt[tid] = 0;
    __syncthreads();

    int n = blockIdx.x * 256 + tid;
    int route = 5;
    bool flip = false;
    if (n < N) {
        const float2* Pp = reinterpret_cast<const float2*>(P) + (size_t)n * 3;
        float2 P0 = Pp[0], P1 = Pp[1], P2 = Pp[2];
        flip = P1.y > P1.x;
        if (flip) {
            float t;
            t = P0.x; P0.x = P0.y; P0.y = t;
            t = P1.x; P1.x = P1.y; P1.y = t;
            t = P2.x; P2.x = -P2.y; P2.y = -t;
        }
        float d0 = fabsf(P0.y - P0.x);
        float d1 = fabsf(P1.y - P1.x);
        float d2 = fabsf(P2.y - P2.x);
        bool cont = fmaxf(d0, fmaxf(d1, d2)) < 0.005f;

        float q0 = P1.x, q1 = P1.y;
        float c0 = sqrtf(GAMMA_F * q0 / P0.x);
        float c1 = sqrtf(GAMMA_F * q1 / P0.y);
        float dv = P2.y - P2.x;
        float num = c0 + c1 - 0.33333334f * dv;
        float pz0 = exp2f(0.2f * __log2f(q0));
        float pz1 = exp2f(0.2f * __log2f(q1));
        float den = c0 / pz0 + c1 / pz1;
        float ps = fmaxf(num / den, 1e-8f);
        float ps2 = ps * ps;
        float pstar = ps2 * ps2 * ps;
        bool vac = dv >= 3.0f * (c0 + c1);
        bool dsb = pstar > fmaxf(q0, q1);
        bool drb = pstar < fminf(q0, q1);
        int label = vac ? 3 : (drb ? 1 : (dsb ? 0 : 2));
        route = cont ? 4 : label;

        if (route >= 3) {
            float* op = out + (size_t)n * 3;
            if (route == 3) {
                op[0] = 0.0f; op[1] = 0.0f; op[2] = 0.0f;
            } else {
                const float2* Up = reinterpret_cast<const float2*>(U) + (size_t)n * 3;
                const float2* Fp = reinterpret_cast<const float2*>(F) + (size_t)n * 3;
                float2 U0 = Up[0], U1 = Up[1], U2 = Up[2];
                float2 F0 = Fp[0], F1 = Fp[1], F2 = Fp[2];
                if (flip) {
                    float t;
                    t = U0.x; U0.x = U0.y; U0.y = t;
                    t = U1.x; U1.x = U1.y; U1.y = t;
                    t = U2.x; U2.x = -U2.y; U2.y = -t;
                    t = F0.x; F0.x = -F0.y; F0.y = -t;
                    t = F1.x; F1.x = -F1.y; F1.y = -t;
                    t = F2.x; F2.x = F2.y;  F2.y = t;
                }
                float cx = cmax[n], cnn = cmin[n];
                float inv = 1.0f / (cx - cnn);
                float cc = cx * cnn;
                float o0 = (cx * F0.x - cnn * F0.y + cc * (U0.y - U0.x)) * inv;
                float o1 = (cx * F1.x - cnn * F1.y + cc * (U1.y - U1.x)) * inv;
                float o2 = (cx * F2.x - cnn * F2.y + cc * (U2.y - U2.x)) * inv;
                if (flip) { o0 = -o0; o1 = -o1; }
                op[0] = o0; op[1] = o1; op[2] = o2;
            }
        }
    }

    int lane = tid & 31, w = tid >> 5;
    int myrank = 0;
#pragma unroll
    for (int r = 0; r < 3; r++) {
        unsigned bal = __ballot_sync(0xffffffffu, route == r);
        if (route == r) myrank = __popc(bal & ((1u << lane) - 1u));
        if (lane == 0 && bal) wBase[w][r] = atomicAdd(&shCnt[r], __popc(bal));
    }
    __syncthreads();
    if (tid < 3) shBase[tid] = atomicAdd(&g_cnt[tid], shCnt[tid]);
    __syncthreads();
    if (route < 3) {
        int pos = shBase[route] + wBase[w][route] + myrank;
        g_bucket[route * NC + pos] = n;
    }

    // ---- blocks 0..2: stage tf32-converted weights for route r
    int r = blockIdx.x;
    if (r < 3) {
        const float* W1r = (r == 0) ? W1_0 : (r == 1) ? W1_1 : W1_2;
        const float* b1r = (r == 0) ? b1_0 : (r == 1) ? b1_1 : b1_2;
        const float* W2r = (r == 0) ? W2_0 : (r == 1) ? W2_1 : W2_2;
        const float* b2r = (r == 0) ? b2_0 : (r == 1) ? b2_1 : b2_2;
        for (int idx = tid; idx < KDIM * SB_STRIDE; idx += 256) {
            int k = idx / SB_STRIDE;
            int c = idx - k * SB_STRIDE;
            float v = 0.0f;
            if (c < 64) {
                if (k < 20)       v = __uint_as_float(f2tf32(W1r[k * 64 + c]));
                else if (k == 20) v = __uint_as_float(f2tf32(b1r[c]));
            }
            g_pB[r][idx] = v;
        }
        if (tid < 256) {
            int j = tid >> 2, kk = tid & 3;
            g_pW2[r][tid] = (kk < 3) ? W2r[j * 3 + kk] : 0.0f;
        }
        if (tid < 4) g_pB2[r][tid] = (tid < 3) ? b2r[tid] : 0.0f;
    }
}

// ---------------------------------------------------------------------------
// Gather one cell, flip, write tf32 feature row to sA; return meta via refs.
__device__ __forceinline__ void gather_store(
    int cell, const float* __restrict__ P, const float* __restrict__ U,
    const float* __restrict__ F, const float* __restrict__ cmax,
    const float* __restrict__ cmin, float* __restrict__ rowPtr, bool& flip)
{
    const float2* Pp = reinterpret_cast<const float2*>(P) + (size_t)cell * 3;
    const float2* Up = reinterpret_cast<const float2*>(U) + (size_t)cell * 3;
    const float2* Fp = reinterpret_cast<const float2*>(F) + (size_t)cell * 3;
    float2 P0 = Pp[0], P1 = Pp[1], P2 = Pp[2];
    float2 U0 = Up[0], U1 = Up[1], U2 = Up[2];
    float2 F0 = Fp[0], F1 = Fp[1], F2 = Fp[2];
    float cx = cmax[cell];
    float cnn = cmin[cell];

    flip = P1.y > P1.x;
    if (flip) {
        float t;
        t = P0.x; P0.x = P0.y; P0.y = t;
        t = P1.x; P1.x = P1.y; P1.y = t;
        t = P2.x; P2.x = -P2.y; P2.y = -t;
        t = U0.x; U0.x = U0.y; U0.y = t;
        t = U1.x; U1.x = U1.y; U1.y = t;
        t = U2.x; U2.x = -U2.y; U2.y = -t;
        t = F0.x; F0.x = -F0.y; F0.y = -t;
        t = F1.x; F1.x = -F1.y; F1.y = -t;
        t = F2.x; F2.x = F2.y;  F2.y = t;
    }
    float4* r4 = reinterpret_cast<float4*>(rowPtr);
    r4[0] = make_float4(__uint_as_float(f2tf32(P0.x)), __uint_as_float(f2tf32(P0.y)),
                        __uint_as_float(f2tf32(P1.x)), __uint_as_float(f2tf32(P1.y)));
    r4[1] = make_float4(__uint_as_float(f2tf32(P2.x)), __uint_as_float(f2tf32(P2.y)),
                        __uint_as_float(f2tf32(U0.x)), __uint_as_float(f2tf32(U0.y)));
    r4[2] = make_float4(__uint_as_float(f2tf32(U1.x)), __uint_as_float(f2tf32(U1.y)),
                        __uint_as_float(f2tf32(U2.x)), __uint_as_float(f2tf32(U2.y)));
    r4[3] = make_float4(__uint_as_float(f2tf32(F0.x)), __uint_as_float(f2tf32(F0.y)),
                        __uint_as_float(f2tf32(F1.x)), __uint_as_float(f2tf32(F1.y)));
    r4[4] = make_float4(__uint_as_float(f2tf32(F2.x)), __uint_as_float(f2tf32(F2.y)),
                        __uint_as_float(f2tf32(cx)),   __uint_as_float(f2tf32(cnn)));
    r4[5] = make_float4(1.0f, 0.0f, 0.0f, 0.0f);       // bias column k=20
}

__global__ __launch_bounds__(256, 3)
void k_mlp(
    const float* __restrict__ P, const float* __restrict__ U,
    const float* __restrict__ F,
    const float* __restrict__ cmax, const float* __restrict__ cmin,
    float* __restrict__ out, int N)
{
    __shared__ __align__(16) float sA[8][64 * SA_STRIDE];   // 57.3 KB
    __shared__ __align__(16) float sB[KDIM * SB_STRIDE];
    __shared__ __align__(16) float sw2[256];
    __shared__ float sb2[3];

    int tid = threadIdx.x;
    int wid = tid >> 5;
    int lane = tid & 31;
    int g = lane >> 2;
    int tig = lane & 3;

    int c0 = g_cnt[0], c1 = g_cnt[1], c2 = g_cnt[2];
    int t0 = (c0 + TILE - 1) / TILE;
    int t1 = (c1 + TILE - 1) / TILE;
    int t2 = (c2 + TILE - 1) / TILE;
    int b = blockIdx.x;
    int total = t0 + t1 + t2;

    if (b >= total) {
        __threadfence();
        if (tid == 0) {
            int old = atomicAdd(&g_done, 1);
            if (old == (int)gridDim.x - 1) {
                g_cnt[0] = 0; g_cnt[1] = 0; g_cnt[2] = 0;
                __threadfence();
                g_done = 0;
            }
        }
        return;
    }

    int route, tileIdx, cnt;
    if (b < t0)           { route = 0; tileIdx = b;           cnt = c0; }
    else if (b < t0 + t1) { route = 1; tileIdx = b - t0;      cnt = c1; }
    else                  { route = 2; tileIdx = b - t0 - t1; cnt = c2; }

    // ---- issue both bucket-index loads FIRST (long chains start early)
    int slot0 = tileIdx * TILE + wid * 64 + lane;        // subtile A
    int slot1 = slot0 + 32;                              // subtile B
    bool valid0 = slot0 < cnt;
    bool valid1 = slot1 < cnt;
    int cell0 = g_bucket[route * NC + (valid0 ? slot0 : (cnt - 1))];
    int cell1 = g_bucket[route * NC + (valid1 ? slot1 : (cnt - 1))];

    // ---- weight copy overlaps the index-load latency
    {
        const float4* src = reinterpret_cast<const float4*>(g_pB[route]);
        float4* dst = reinterpret_cast<float4*>(sB);
        const int nv = (KDIM * SB_STRIDE) / 4;     // 432
        for (int i = tid; i < nv; i += 256) dst[i] = src[i];
        const float4* s2 = reinterpret_cast<const float4*>(g_pW2[route]);
        float4* d2 = reinterpret_cast<float4*>(sw2);
        if (tid < 64) d2[tid] = s2[tid];
        if (tid < 3) sb2[tid] = g_pB2[route][tid];
    }

    // ---- gather both cells, stage features
    bool flip0, flip1;
    gather_store(cell0, P, U, F, cmax, cmin, &sA[wid][lane * SA_STRIDE], flip0);
    gather_store(cell1, P, U, F, cmax, cmin, &sA[wid][(32 + lane) * SA_STRIDE], flip1);
    unsigned flipm[2], validm[2];
    flipm[0]  = __ballot_sync(0xffffffffu, flip0);
    flipm[1]  = __ballot_sync(0xffffffffu, flip1);
    validm[0] = __ballot_sync(0xffffffffu, valid0);
    validm[1] = __ballot_sync(0xffffffffu, valid1);
    __syncthreads();

    // ---- two 32-cell subtiles per warp
#pragma unroll
    for (int sub = 0; sub < 2; sub++) {
        const float* sAw = &sA[wid][sub * 32 * SA_STRIDE];

        float os[2][2][3];
#pragma unroll
        for (int m = 0; m < 2; m++)
#pragma unroll
            for (int r = 0; r < 2; r++)
#pragma unroll
                for (int c = 0; c < 3; c++) os[m][r][c] = 0.0f;

#pragma unroll
        for (int h = 0; h < 2; h++) {
            float d[2][4][4];
#pragma unroll
            for (int m = 0; m < 2; m++)
#pragma unroll
                for (int nt = 0; nt < 4; nt++)
#pragma unroll
                    for (int v = 0; v < 4; v++) d[m][nt][v] = 0.0f;

#pragma unroll
            for (int kt = 0; kt < 3; kt++) {
                int ak = g * SA_STRIDE + kt * 8 + tig;
                uint32_t a[2][4];
#pragma unroll
                for (int m = 0; m < 2; m++) {
                    int base = ak + m * 16 * SA_STRIDE;
                    a[m][0] = __float_as_uint(sAw[base]);
                    a[m][1] = __float_as_uint(sAw[base + 8 * SA_STRIDE]);
                    a[m][2] = __float_as_uint(sAw[base + 4]);
                    a[m][3] = __float_as_uint(sAw[base + 8 * SA_STRIDE + 4]);
                }
                int bk = (kt * 8 + tig) * SB_STRIDE + h * 32 + g;
#pragma unroll
                for (int nt = 0; nt < 4; nt++) {
                    uint32_t b0 = __float_as_uint(sB[bk + nt * 8]);
                    uint32_t b1 = __float_as_uint(sB[bk + 4 * SB_STRIDE + nt * 8]);
#pragma unroll
                    for (int m = 0; m < 2; m++)
                        mma_tf32_k8(d[m][nt], a[m][0], a[m][1], a[m][2], a[m][3], b0, b1);
                }
            }

            // epilogue for this half: MUFU tanh + layer-2 partials
#pragma unroll
            for (int nt = 0; nt < 4; nt++) {
                int j0 = (h * 4 + nt) * 8 + 2 * tig;
                float4 w2a = *reinterpret_cast<const float4*>(sw2 + j0 * 4);
                float4 w2b = *reinterpret_cast<const float4*>(sw2 + j0 * 4 + 4);
#pragma unroll
                for (int m = 0; m < 2; m++) {
                    float ta = tanh_mufu(d[m][nt][0]);
                    float tb = tanh_mufu(d[m][nt][1]);
                    float tc = tanh_mufu(d[m][nt][2]);
                    float td = tanh_mufu(d[m][nt][3]);
                    os[m][0][0] = fmaf(ta, w2a.x, fmaf(tb, w2b.x, os[m][0][0]));
                    os[m][0][1] = fmaf(ta, w2a.y, fmaf(tb, w2b.y, os[m][0][1]));
                    os[m][0][2] = fmaf(ta, w2a.z, fmaf(tb, w2b.z, os[m][0][2]));
                    os[m][1][0] = fmaf(tc, w2a.x, fmaf(td, w2b.x, os[m][1][0]));
                    os[m][1][1] = fmaf(tc, w2a.y, fmaf(td, w2b.y, os[m][1][1]));
                    os[m][1][2] = fmaf(tc, w2a.z, fmaf(td, w2b.z, os[m][1][2]));
                }
            }
        }

        // quad reduce (lanes xor 1, xor 2 share the same output row g)
#pragma unroll
        for (int m = 0; m < 2; m++)
#pragma unroll
            for (int r = 0; r < 2; r++)
#pragma unroll
                for (int c = 0; c < 3; c++) {
                    float v = os[m][r][c];
                    v += __shfl_xor_sync(0xffffffffu, v, 1);
                    v += __shfl_xor_sync(0xffffffffu, v, 2);
                    os[m][r][c] = v;
                }

        // lane q = lane&3 writes warp-local cell  (q>>1)*16 + (q&1)*8 + g
        int q = lane & 3;
        int mm = q >> 1, rr = q & 1;
        int cl = mm * 16 + rr * 8 + g;
        float o0 = os[mm][rr][0] + sb2[0];
        float o1 = os[mm][rr][1] + sb2[1];
        float o2 = os[mm][rr][2] + sb2[2];
        if ((flipm[sub] >> cl) & 1) { o0 = -o0; o1 = -o1; }
        int cellid = __shfl_sync(0xffffffffu, sub ? cell1 : cell0, cl);
        if ((validm[sub] >> cl) & 1) {
            float* op = out + (size_t)cellid * 3;
            op[0] = o0; op[1] = o1; op[2] = o2;
        }
    }

    // ---- counter self-reset (last CTA)
    __syncthreads();
    __threadfence();
    if (tid == 0) {
        int old = atomicAdd(&g_done, 1);
        if (old == (int)gridDim.x - 1) {
            g_cnt[0] = 0; g_cnt[1] = 0; g_cnt[2] = 0;
            __threadfence();
            g_done = 0;
        }
    }
}

// ---------------------------------------------------------------------------
extern "C" void kernel_launch(void* const* d_in, const int* in_sizes, int n_in,
                              void* d_out, int out_size) {
    const float* P    = (const float*)d_in[0];
    const float* U    = (const float*)d_in[1];
    const float* F    = (const float*)d_in[2];
    const float* cmax = (const float*)d_in[3];
    const float* cmin = (const float*)d_in[4];
    const float* W1_ds = (const float*)d_in[5];
    const float* b1_ds = (const float*)d_in[6];
    const float* W2_ds = (const float*)d_in[7];
    const float* b2_ds = (const float*)d_in[8];
    const float* W1_dr = (const float*)d_in[9];
    const float* b1_dr = (const float*)d_in[10];
    const float* W2_dr = (const float*)d_in[11];
    const float* b2_dr = (const float*)d_in[12];
    const float* W1_rs = (const float*)d_in[13];
    const float* b1_rs = (const float*)d_in[14];
    const float* W2_rs = (const float*)d_in[15];
    const float* b2_rs = (const float*)d_in[16];

    int N = in_sizes[3];
    float* out = (float*)d_out;

    k_classify<<<(N + 255) / 256, 256>>>(
        P, U, F, cmax, cmin,
        W1_ds, b1_ds, W2_ds, b2_ds,
        W1_dr, b1_dr, W2_dr, b2_dr,
        W1_rs, b1_rs, W2_rs, b2_rs,
        out, N);
    int grid2 = (N + TILE - 1) / TILE + 3;
    k_mlp<<<grid2, 256>>>(P, U, F, cmax, cmin, out, N);
}

// round 16
// speedup vs baseline: 1.1344x; 1.1344x over previous
#include <cuda_runtime.h>
#include <cstdint>

// RiemannSolver R15: persistent warp-autonomous software-pipelined k_mlp.
// Each warp owns an independent stream of 32-cell route-uniform tiles,
// double-buffered in its private sA slice: stage(t) -> issue gather(t+W) ->
// MMA(t). No per-tile CTA barriers. Weights for all 3 routes staged once per
// persistent CTA. k_classify unchanged (routes + buckets + tf32 weight prep).

typedef unsigned long long u64;

#define NC 1048576
#define GAMMA_F 1.6666666666666667f
#define KDIM 24
#define SA_STRIDE 28      // floats/row: conflict-free STS.128 + A-frag LDS
#define SB_STRIDE 72      // floats/row: 72%32==8 -> conflict-free B-frag LDS
#define GRID2 296         // persistent: 2 CTAs/SM target

__device__ int g_cnt[4];
__device__ int g_done;
__device__ int g_bucket[3 * NC];
__device__ float g_pB[3][KDIM * SB_STRIDE];
__device__ float g_pW2[3][256];
__device__ float g_pB2[3][4];

__device__ __forceinline__ uint32_t f2tf32(float x) {
    uint32_t r;
    asm("cvt.rna.tf32.f32 %0, %1;" : "=r"(r) : "f"(x));
    return r;
}

// m16n8k8 tf32 (mapping verified R8..R14):
//  A: a0=(g,tig) a1=(g+8,tig) a2=(g,tig+4) a3=(g+8,tig+4)
//  B: b0=(tig,n) b1=(tig+4,n)
//  D: d0=(g,2tig) d1=(g,2tig+1) d2=(g+8,2tig) d3=(g+8,2tig+1)
__device__ __forceinline__ void mma_tf32_k8(float* d, uint32_t a0, uint32_t a1,
                                            uint32_t a2, uint32_t a3,
                                            uint32_t b0, uint32_t b1) {
    asm volatile(
        "mma.sync.aligned.m16n8k8.row.col.f32.tf32.tf32.f32 "
        "{%0,%1,%2,%3}, {%4,%5,%6,%7}, {%8,%9}, {%0,%1,%2,%3};"
        : "+f"(d[0]), "+f"(d[1]), "+f"(d[2]), "+f"(d[3])
        : "r"(a0), "r"(a1), "r"(a2), "r"(a3), "r"(b0), "r"(b1));
}

__device__ __forceinline__ float tanh_mufu(float x) {
    float r;
    asm("tanh.approx.f32 %0, %1;" : "=f"(r) : "f"(x));
    return r;
}

// ---------------------------------------------------------------------------
__global__ __launch_bounds__(256)
void k_classify(const float* __restrict__ P, const float* __restrict__ U,
                const float* __restrict__ F, const float* __restrict__ cmax,
                const float* __restrict__ cmin,
                const float* __restrict__ W1_0, const float* __restrict__ b1_0,
                const float* __restrict__ W2_0, const float* __restrict__ b2_0,
                const float* __restrict__ W1_1, const float* __restrict__ b1_1,
                const float* __restrict__ W2_1, const float* __restrict__ b2_1,
                const float* __restrict__ W1_2, const float* __restrict__ b1_2,
                const float* __restrict__ W2_2, const float* __restrict__ b2_2,
                float* __restrict__ out, int N) {
    __shared__ int shCnt[3];
    __shared__ int shBase[3];
    __shared__ int wBase[8][3];
    int tid = threadIdx.x;
    if (tid < 3) shCnt[tid] = 0;
    __syncthreads();

    int n = blockIdx.x * 256 + tid;
    int route = 5;
    bool flip = false;
    if (n < N) {
        const float2* Pp = reinterpret_cast<const float2*>(P) + (size_t)n * 3;
        float2 P0 = Pp[0], P1 = Pp[1], P2 = Pp[2];
        flip = P1.y > P1.x;
        if (flip) {
            float t;
            t = P0.x; P0.x = P0.y; P0.y = t;
            t = P1.x; P1.x = P1.y; P1.y = t;
            t = P2.x; P2.x = -P2.y; P2.y = -t;
        }
        float d0 = fabsf(P0.y - P0.x);
        float d1 = fabsf(P1.y - P1.x);
        float d2 = fabsf(P2.y - P2.x);
        bool cont = fmaxf(d0, fmaxf(d1, d2)) < 0.005f;

        float q0 = P1.x, q1 = P1.y;
        float c0 = sqrtf(GAMMA_F * q0 / P0.x);
        float c1 = sqrtf(GAMMA_F * q1 / P0.y);
        float dv = P2.y - P2.x;
        float num = c0 + c1 - 0.33333334f * dv;
        float pz0 = exp2f(0.2f * __log2f(q0));
        float pz1 = exp2f(0.2f * __log2f(q1));
        float den = c0 / pz0 + c1 / pz1;
        float ps = fmaxf(num / den, 1e-8f);
        float ps2 = ps * ps;
        float pstar = ps2 * ps2 * ps;
        bool vac = dv >= 3.0f * (c0 + c1);
        bool dsb = pstar > fmaxf(q0, q1);
        bool drb = pstar < fminf(q0, q1);
        int label = vac ? 3 : (drb ? 1 : (dsb ? 0 : 2));
        route = cont ? 4 : label;

        if (route >= 3) {
            float* op = out + (size_t)n * 3;
            if (route == 3) {
                op[0] = 0.0f; op[1] = 0.0f; op[2] = 0.0f;
            } else {
                const float2* Up = reinterpret_cast<const float2*>(U) + (size_t)n * 3;
                const float2* Fp = reinterpret_cast<const float2*>(F) + (size_t)n * 3;
                float2 U0 = Up[0], U1 = Up[1], U2 = Up[2];
                float2 F0 = Fp[0], F1 = Fp[1], F2 = Fp[2];
                if (flip) {
                    float t;
                    t = U0.x; U0.x = U0.y; U0.y = t;
                    t = U1.x; U1.x = U1.y; U1.y = t;
                    t = U2.x; U2.x = -U2.y; U2.y = -t;
                    t = F0.x; F0.x = -F0.y; F0.y = -t;
                    t = F1.x; F1.x = -F1.y; F1.y = -t;
                    t = F2.x; F2.x = F2.y;  F2.y = t;
                }
                float cx = cmax[n], cnn = cmin[n];
                float inv = 1.0f / (cx - cnn);
                float cc = cx * cnn;
                float o0 = (cx * F0.x - cnn * F0.y + cc * (U0.y - U0.x)) * inv;
                float o1 = (cx * F1.x - cnn * F1.y + cc * (U1.y - U1.x)) * inv;
                float o2 = (cx * F2.x - cnn * F2.y + cc * (U2.y - U2.x)) * inv;
                if (flip) { o0 = -o0; o1 = -o1; }
                op[0] = o0; op[1] = o1; op[2] = o2;
            }
        }
    }

    int lane = tid & 31, w = tid >> 5;
    int myrank = 0;
#pragma unroll
    for (int r = 0; r < 3; r++) {
        unsigned bal = __ballot_sync(0xffffffffu, route == r);
        if (route == r) myrank = __popc(bal & ((1u << lane) - 1u));
        if (lane == 0 && bal) wBase[w][r] = atomicAdd(&shCnt[r], __popc(bal));
    }
    __syncthreads();
    if (tid < 3) shBase[tid] = atomicAdd(&g_cnt[tid], shCnt[tid]);
    __syncthreads();
    if (route < 3) {
        int pos = shBase[route] + wBase[w][route] + myrank;
        g_bucket[route * NC + pos] = n;
    }

    // ---- blocks 0..2: stage tf32-converted weights for route r
    int r = blockIdx.x;
    if (r < 3) {
        const float* W1r = (r == 0) ? W1_0 : (r == 1) ? W1_1 : W1_2;
        const float* b1r = (r == 0) ? b1_0 : (r == 1) ? b1_1 : b1_2;
        const float* W2r = (r == 0) ? W2_0 : (r == 1) ? W2_1 : W2_2;
        const float* b2r = (r == 0) ? b2_0 : (r == 1) ? b2_1 : b2_2;
        for (int idx = tid; idx < KDIM * SB_STRIDE; idx += 256) {
            int k = idx / SB_STRIDE;
            int c = idx - k * SB_STRIDE;
            float v = 0.0f;
            if (c < 64) {
                if (k < 20)       v = __uint_as_float(f2tf32(W1r[k * 64 + c]));
                else if (k == 20) v = __uint_as_float(f2tf32(b1r[c]));
            }
            g_pB[r][idx] = v;
        }
        if (tid < 256) {
            int j = tid >> 2, kk = tid & 3;
            g_pW2[r][tid] = (kk < 3) ? W2r[j * 3 + kk] : 0.0f;
        }
        if (tid < 4) g_pB2[r][tid] = (tid < 3) ? b2r[tid] : 0.0f;
    }
}

// ---------------------------------------------------------------------------
struct GR {
    float f[20];
    int cell;
    int route;
    bool flip;
    bool valid;
};

__device__ __forceinline__ GR do_gather(
    int t, int T0, int T01, int c0, int c1, int c2, int lane,
    const float* __restrict__ P, const float* __restrict__ U,
    const float* __restrict__ F, const float* __restrict__ cmax,
    const float* __restrict__ cmin)
{
    GR r;
    int route = (t >= T0) + (t >= T01);
    int tb  = (route == 0) ? 0  : (route == 1) ? T0 : T01;
    int cnt = (route == 0) ? c0 : (route == 1) ? c1 : c2;
    int slot = (t - tb) * 32 + lane;
    r.valid = slot < cnt;
    int cslot = r.valid ? slot : (cnt - 1);
    int cell = g_bucket[route * NC + cslot];
    r.cell = cell;
    r.route = route;

    const float2* Pp = reinterpret_cast<const float2*>(P) + (size_t)cell * 3;
    const float2* Up = reinterpret_cast<const float2*>(U) + (size_t)cell * 3;
    const float2* Fp = reinterpret_cast<const float2*>(F) + (size_t)cell * 3;
    float2 P0 = Pp[0], P1 = Pp[1], P2 = Pp[2];
    float2 U0 = Up[0], U1 = Up[1], U2 = Up[2];
    float2 F0 = Fp[0], F1 = Fp[1], F2 = Fp[2];
    float cx = cmax[cell];
    float cnn = cmin[cell];

    bool flip = P1.y > P1.x;
    r.flip = flip;
    if (flip) {
        float t2;
        t2 = P0.x; P0.x = P0.y; P0.y = t2;
        t2 = P1.x; P1.x = P1.y; P1.y = t2;
        t2 = P2.x; P2.x = -P2.y; P2.y = -t2;
        t2 = U0.x; U0.x = U0.y; U0.y = t2;
        t2 = U1.x; U1.x = U1.y; U1.y = t2;
        t2 = U2.x; U2.x = -U2.y; U2.y = -t2;
        t2 = F0.x; F0.x = -F0.y; F0.y = -t2;
        t2 = F1.x; F1.x = -F1.y; F1.y = -t2;
        t2 = F2.x; F2.x = F2.y;  F2.y = t2;
    }
    r.f[0]  = __uint_as_float(f2tf32(P0.x));  r.f[1]  = __uint_as_float(f2tf32(P0.y));
    r.f[2]  = __uint_as_float(f2tf32(P1.x));  r.f[3]  = __uint_as_float(f2tf32(P1.y));
    r.f[4]  = __uint_as_float(f2tf32(P2.x));  r.f[5]  = __uint_as_float(f2tf32(P2.y));
    r.f[6]  = __uint_as_float(f2tf32(U0.x));  r.f[7]  = __uint_as_float(f2tf32(U0.y));
    r.f[8]  = __uint_as_float(f2tf32(U1.x));  r.f[9]  = __uint_as_float(f2tf32(U1.y));
    r.f[10] = __uint_as_float(f2tf32(U2.x));  r.f[11] = __uint_as_float(f2tf32(U2.y));
    r.f[12] = __uint_as_float(f2tf32(F0.x));  r.f[13] = __uint_as_float(f2tf32(F0.y));
    r.f[14] = __uint_as_float(f2tf32(F1.x));  r.f[15] = __uint_as_float(f2tf32(F1.y));
    r.f[16] = __uint_as_float(f2tf32(F2.x));  r.f[17] = __uint_as_float(f2tf32(F2.y));
    r.f[18] = __uint_as_float(f2tf32(cx));    r.f[19] = __uint_as_float(f2tf32(cnn));
    return r;
}

__device__ __forceinline__ void mma_tile(
    const float* __restrict__ sAw, const float* __restrict__ sBr,
    const float* __restrict__ w2r, const float* __restrict__ b2r,
    unsigned flipm, unsigned validm, int cell, int lane, int g, int tig,
    float* __restrict__ out)
{
    float os[2][2][3];
#pragma unroll
    for (int m = 0; m < 2; m++)
#pragma unroll
        for (int r = 0; r < 2; r++)
#pragma unroll
            for (int c = 0; c < 3; c++) os[m][r][c] = 0.0f;

#pragma unroll
    for (int h = 0; h < 2; h++) {
        float d[2][4][4];
#pragma unroll
        for (int m = 0; m < 2; m++)
#pragma unroll
            for (int nt = 0; nt < 4; nt++)
#pragma unroll
                for (int v = 0; v < 4; v++) d[m][nt][v] = 0.0f;

#pragma unroll
        for (int kt = 0; kt < 3; kt++) {
            int ak = g * SA_STRIDE + kt * 8 + tig;
            uint32_t a[2][4];
#pragma unroll
            for (int m = 0; m < 2; m++) {
                int base = ak + m * 16 * SA_STRIDE;
                a[m][0] = __float_as_uint(sAw[base]);
                a[m][1] = __float_as_uint(sAw[base + 8 * SA_STRIDE]);
                a[m][2] = __float_as_uint(sAw[base + 4]);
                a[m][3] = __float_as_uint(sAw[base + 8 * SA_STRIDE + 4]);
            }
            int bk = (kt * 8 + tig) * SB_STRIDE + h * 32 + g;
#pragma unroll
            for (int nt = 0; nt < 4; nt++) {
                uint32_t b0 = __float_as_uint(sBr[bk + nt * 8]);
                uint32_t b1 = __float_as_uint(sBr[bk + 4 * SB_STRIDE + nt * 8]);
#pragma unroll
                for (int m = 0; m < 2; m++)
                    mma_tf32_k8(d[m][nt], a[m][0], a[m][1], a[m][2], a[m][3], b0, b1);
            }
        }

#pragma unroll
        for (int nt = 0; nt < 4; nt++) {
            int j0 = (h * 4 + nt) * 8 + 2 * tig;
            float4 w2a = *reinterpret_cast<const float4*>(w2r + j0 * 4);
            float4 w2b = *reinterpret_cast<const float4*>(w2r + j0 * 4 + 4);
#pragma unroll
            for (int m = 0; m < 2; m++) {
                float ta = tanh_mufu(d[m][nt][0]);
                float tb = tanh_mufu(d[m][nt][1]);
                float tc = tanh_mufu(d[m][nt][2]);
                float td = tanh_mufu(d[m][nt][3]);
                os[m][0][0] = fmaf(ta, w2a.x, fmaf(tb, w2b.x, os[m][0][0]));
                os[m][0][1] = fmaf(ta, w2a.y, fmaf(tb, w2b.y, os[m][0][1]));
                os[m][0][2] = fmaf(ta, w2a.z, fmaf(tb, w2b.z, os[m][0][2]));
                os[m][1][0] = fmaf(tc, w2a.x, fmaf(td, w2b.x, os[m][1][0]));
                os[m][1][1] = fmaf(tc, w2a.y, fmaf(td, w2b.y, os[m][1][1]));
                os[m][1][2] = fmaf(tc, w2a.z, fmaf(td, w2b.z, os[m][1][2]));
            }
        }
    }

    // quad reduce (lanes xor 1, xor 2 share the same output row g)
#pragma unroll
    for (int m = 0; m < 2; m++)
#pragma unroll
        for (int r = 0; r < 2; r++)
#pragma unroll
            for (int c = 0; c < 3; c++) {
                float v = os[m][r][c];
                v += __shfl_xor_sync(0xffffffffu, v, 1);
                v += __shfl_xor_sync(0xffffffffu, v, 2);
                os[m][r][c] = v;
            }

    // lane q = lane&3 writes warp-local cell (q>>1)*16 + (q&1)*8 + g
    int q = lane & 3;
    int mm = q >> 1, rr = q & 1;
    int cl = mm * 16 + rr * 8 + g;
    float o0 = os[mm][rr][0] + b2r[0];
    float o1 = os[mm][rr][1] + b2r[1];
    float o2 = os[mm][rr][2] + b2r[2];
    if ((flipm >> cl) & 1) { o0 = -o0; o1 = -o1; }
    int cellid = __shfl_sync(0xffffffffu, cell, cl);
    if ((validm >> cl) & 1) {
        float* op = out + (size_t)cellid * 3;
        op[0] = o0; op[1] = o1; op[2] = o2;
    }
}

__global__ __launch_bounds__(256)
void k_mlp(
    const float* __restrict__ P, const float* __restrict__ U,
    const float* __restrict__ F,
    const float* __restrict__ cmax, const float* __restrict__ cmin,
    float* __restrict__ out, int N)
{
    __shared__ __align__(16) float sA[8][2][32 * SA_STRIDE];  // 57.3 KB
    __shared__ __align__(16) float sB3[3][KDIM * SB_STRIDE];  // 20.7 KB
    __shared__ __align__(16) float sw23[3][256];              // 3 KB
    __shared__ float sb23[3][4];

    int tid = threadIdx.x;
    int wid = tid >> 5;
    int lane = tid & 31;
    int g = lane >> 2;
    int tig = lane & 3;

    int c0 = g_cnt[0], c1 = g_cnt[1], c2 = g_cnt[2];
    int T0 = (c0 + 31) >> 5;
    int T1 = (c1 + 31) >> 5;
    int T2 = (c2 + 31) >> 5;
    int TT = T0 + T1 + T2;
    int T01 = T0 + T1;

    // ---- one-time weight staging (all 3 routes)
    {
        const float4* src = reinterpret_cast<const float4*>(&g_pB[0][0]);
        float4* dst = reinterpret_cast<float4*>(&sB3[0][0]);
        const int nv = 3 * (KDIM * SB_STRIDE) / 4;   // 1296
        for (int i = tid; i < nv; i += 256) dst[i] = src[i];
        const float4* s2 = reinterpret_cast<const float4*>(&g_pW2[0][0]);
        float4* d2 = reinterpret_cast<float4*>(&sw23[0][0]);
        if (tid < 192) d2[tid] = s2[tid];
        if (tid < 12) (&sb23[0][0])[tid] = (&g_pB2[0][0])[tid];
    }
    __syncthreads();

    // ---- per-warp pipelined tile stream
    int w = blockIdx.x * 8 + wid;
    const int W = gridDim.x * 8;
    int t = w;
    GR gr;
    if (t < TT) gr = do_gather(t, T0, T01, c0, c1, c2, lane, P, U, F, cmax, cmin);
    int buf = 0;

    while (t < TT) {
        // stage current tile into this warp's buffer
        {
            float4* r4 = reinterpret_cast<float4*>(&sA[wid][buf][lane * SA_STRIDE]);
            r4[0] = make_float4(gr.f[0],  gr.f[1],  gr.f[2],  gr.f[3]);
            r4[1] = make_float4(gr.f[4],  gr.f[5],  gr.f[6],  gr.f[7]);
            r4[2] = make_float4(gr.f[8],  gr.f[9],  gr.f[10], gr.f[11]);
            r4[3] = make_float4(gr.f[12], gr.f[13], gr.f[14], gr.f[15]);
            r4[4] = make_float4(gr.f[16], gr.f[17], gr.f[18], gr.f[19]);
            r4[5] = make_float4(1.0f, 0.0f, 0.0f, 0.0f);   // bias col k=20
        }
        unsigned flipm  = __ballot_sync(0xffffffffu, gr.flip);
        unsigned validm = __ballot_sync(0xffffffffu, gr.valid);
        int cell_c = gr.cell;
        int rt = gr.route;

        // issue next tile's gather; its latency hides under the MMA below
        int tn = t + W;
        if (tn < TT)
            gr = do_gather(tn, T0, T01, c0, c1, c2, lane, P, U, F, cmax, cmin);

        __syncwarp();
        mma_tile(&sA[wid][buf][0], &sB3[rt][0], &sw23[rt][0], &sb23[rt][0],
                 flipm, validm, cell_c, lane, g, tig, out);
        buf ^= 1;
        t = tn;
    }

    // ---- counter self-reset (last CTA)
    __syncthreads();
    __threadfence();
    if (tid == 0) {
        int old = atomicAdd(&g_done, 1);
        if (old == (int)gridDim.x - 1) {
            g_cnt[0] = 0; g_cnt[1] = 0; g_cnt[2] = 0;
            __threadfence();
            g_done = 0;
        }
    }
}

// ---------------------------------------------------------------------------
extern "C" void kernel_launch(void* const* d_in, const int* in_sizes, int n_in,
                              void* d_out, int out_size) {
    const float* P    = (const float*)d_in[0];
    const float* U    = (const float*)d_in[1];
    const float* F    = (const float*)d_in[2];
    const float* cmax = (const float*)d_in[3];
    const float* cmin = (const float*)d_in[4];
    const float* W1_ds = (const float*)d_in[5];
    const float* b1_ds = (const float*)d_in[6];
    const float* W2_ds = (const float*)d_in[7];
    const float* b2_ds = (const float*)d_in[8];
    const float* W1_dr = (const float*)d_in[9];
    const float* b1_dr = (const float*)d_in[10];
    const float* W2_dr = (const float*)d_in[11];
    const float* b2_dr = (const float*)d_in[12];
    const float* W1_rs = (const float*)d_in[13];
    const float* b1_rs = (const float*)d_in[14];
    const float* W2_rs = (const float*)d_in[15];
    const float* b2_rs = (const float*)d_in[16];

    int N = in_sizes[3];
    float* out = (float*)d_out;

    k_classify<<<(N + 255) / 256, 256>>>(
        P, U, F, cmax, cmin,
        W1_ds, b1_ds, W2_ds, b2_ds,
        W1_dr, b1_dr, W2_dr, b2_dr,
        W1_rs, b1_rs, W2_rs, b2_rs,
        out, N);
    k_mlp<<<GRID2, 256>>>(P, U, F, cmax, cmin, out, N);
}